// round 2
// baseline (speedup 1.0000x reference)
#include <cuda_runtime.h>

// Problem constants
#define T_STEPS 512
#define BATCH   32
#define HID     1024
#define G4      4096   // 4*HID
#define NLAYERS 2

#define NCTA_REC    64
#define REC_THREADS 128

// ---------------------------------------------------------------------------
// Static device scratch (no runtime allocation allowed)
// ---------------------------------------------------------------------------
__device__ float g_xg[(size_t)T_STEPS * BATCH * G4];    // 256 MB: precomputed input projections
__device__ float g_out0[(size_t)T_STEPS * BATCH * HID]; // 64 MB: layer-0 output sequence
__device__ float g_hbuf[2 * BATCH * HID];               // double-buffered hidden state
__device__ unsigned g_bar_count = 0;
__device__ unsigned g_bar_sense = 0;

__device__ __forceinline__ float sigmoidf_(float x) {
    return 1.0f / (1.0f + __expf(-x));
}

// Sense-style grid barrier with monotonic phase. All CTAs must be co-resident
// (64 CTAs <= 148 SMs, 1 CTA/SM trivially). Wrap-safe signed compare.
__device__ __forceinline__ void grid_barrier(unsigned nctas, unsigned phase) {
    __syncthreads();
    if (threadIdx.x == 0) {
        __threadfence();
        unsigned a = atomicAdd(&g_bar_count, 1u);
        if (a == nctas - 1u) {
            atomicExch(&g_bar_count, 0u);
            __threadfence();
            atomicExch(&g_bar_sense, phase);
        } else {
            while ((int)(atomicAdd(&g_bar_sense, 0u) - phase) < 0) {
                __nanosleep(32);
            }
        }
    }
    __syncthreads();
}

// ---------------------------------------------------------------------------
// Projection GEMM: C[m, n] = sum_k A[m,k] * W[n,k] + bi[n]
// A: [M=16384, K=1024] (x for layer 0, g_out0 for layer 1), W: [4096, 1024]
// Writes g_xg. 64x64 tile, 128 threads, 4x8 register blocking.
// ---------------------------------------------------------------------------
__global__ __launch_bounds__(128) void proj_kernel(
    const float* __restrict__ x_in, int layer,
    const float* __restrict__ W, const float* __restrict__ bi)
{
    const float* A = (layer == 0) ? x_in : g_out0;

    __shared__ float a_s[32][64];
    __shared__ float b_s[32][64];

    const int tx = threadIdx.x;
    const int m0 = blockIdx.y * 64;
    const int n0 = blockIdx.x * 64;
    const int tm = tx >> 3;        // 0..15  -> rows tm*4 .. tm*4+3
    const int tn = tx & 7;         // 0..7   -> cols tn*8 .. tn*8+7
    const int lrow  = tx & 63;     // loader: which tile row
    const int lhalf = tx >> 6;     // loader: which 16-wide k chunk

    float acc[4][8];
#pragma unroll
    for (int i = 0; i < 4; i++)
#pragma unroll
        for (int j = 0; j < 8; j++) acc[i][j] = 0.0f;

    const float4* ap = (const float4*)(A + (size_t)(m0 + lrow) * HID + lhalf * 16);
    const float4* bp = (const float4*)(W + (size_t)(n0 + lrow) * HID + lhalf * 16);

    for (int k0 = 0; k0 < HID; k0 += 32) {
        float4 av[4], bv[4];
#pragma unroll
        for (int i = 0; i < 4; i++) { av[i] = __ldg(ap + i); bv[i] = __ldg(bp + i); }
        ap += 8; bp += 8;

        __syncthreads();
#pragma unroll
        for (int i = 0; i < 4; i++) {
            int kk = lhalf * 16 + i * 4;
            a_s[kk + 0][lrow] = av[i].x;
            a_s[kk + 1][lrow] = av[i].y;
            a_s[kk + 2][lrow] = av[i].z;
            a_s[kk + 3][lrow] = av[i].w;
            b_s[kk + 0][lrow] = bv[i].x;
            b_s[kk + 1][lrow] = bv[i].y;
            b_s[kk + 2][lrow] = bv[i].z;
            b_s[kk + 3][lrow] = bv[i].w;
        }
        __syncthreads();

#pragma unroll 8
        for (int kk = 0; kk < 32; kk++) {
            float a4[4], b8[8];
            *(float4*)a4      = *(const float4*)&a_s[kk][tm * 4];
            *(float4*)&b8[0]  = *(const float4*)&b_s[kk][tn * 8];
            *(float4*)&b8[4]  = *(const float4*)&b_s[kk][tn * 8 + 4];
#pragma unroll
            for (int mi = 0; mi < 4; mi++)
#pragma unroll
                for (int ni = 0; ni < 8; ni++)
                    acc[mi][ni] += a4[mi] * b8[ni];
        }
    }

    float bias8[8];
#pragma unroll
    for (int ni = 0; ni < 8; ni++) bias8[ni] = __ldg(bi + n0 + tn * 8 + ni);

#pragma unroll
    for (int mi = 0; mi < 4; mi++) {
        size_t row = (size_t)(m0 + tm * 4 + mi);
        float* cp = g_xg + row * G4 + n0 + tn * 8;
#pragma unroll
        for (int ni = 0; ni < 8; ni++) cp[ni] = acc[mi][ni] + bias8[ni];
    }
}

// ---------------------------------------------------------------------------
// Persistent recurrence kernel. 64 CTAs x 128 threads, device-side t-loop,
// one grid barrier per step. CTA `cta` owns j in [cta*16, cta*16+16) across
// all 4 gate components; thread owns 1 j x 4 batches -> cell state in regs.
// Hidden state is double-buffered in g_hbuf, accessed with .cg (L2) to avoid
// stale L1 across SMs.
// ---------------------------------------------------------------------------
__global__ __launch_bounds__(REC_THREADS) void recur_kernel(
    const float* __restrict__ Rm, const float* __restrict__ bh,
    const float* __restrict__ h0l, const float* __restrict__ c0l,
    int layer, float* __restrict__ out_g,
    float* __restrict__ hfin, float* __restrict__ cfin)
{
    float* out = (layer == 0) ? g_out0 : out_g;

    __shared__ float h_s[64][32];   // [kk][b]
    __shared__ float r_s[64][64];   // [kk][q], q = jj*4 + comp

    const int tx  = threadIdx.x;
    const int cta = blockIdx.x;
    const int jj    = tx >> 3;            // 0..15
    const int jglob = cta * 16 + jj;
    const int b0    = (tx & 7) * 4;       // batch base, 4 batches per thread

    unsigned phase = atomicAdd(&g_bar_sense, 0u);  // stable: no writes before 1st barrier

    // init h buffer 0 from h0 (8192 threads x 4 floats = 32768)
    {
        int gid = cta * REC_THREADS + tx;
        float4 v = *(const float4*)(h0l + (size_t)gid * 4);
        __stcg((float4*)(g_hbuf + (size_t)gid * 4), v);
    }

    float c_reg[4], bhv[4];
#pragma unroll
    for (int bi = 0; bi < 4; bi++) c_reg[bi] = c0l[(b0 + bi) * HID + jglob];
#pragma unroll
    for (int ci = 0; ci < 4; ci++) bhv[ci] = bh[ci * HID + jglob];

    phase++;
    grid_barrier(NCTA_REC, phase);

    // loader roles
    const int hl_b = tx & 31, hl_q = tx >> 5;     // h tile: 32 batches x 4 k-chunks
    const int rl_q = tx & 63, rl_half = tx >> 6;  // R tile: 64 q-rows x 2 k-halves
    const int r_comp = rl_q & 3;
    const int r_grow = r_comp * HID + cta * 16 + (rl_q >> 2);
    const float* Rbase = Rm + (size_t)r_grow * HID + rl_half * 32;

    float hlast[4] = {0.f, 0.f, 0.f, 0.f};

    for (int t = 0; t < T_STEPS; t++) {
        const float* hb = g_hbuf + (t & 1) * (BATCH * HID);
        float*       hn = g_hbuf + ((t + 1) & 1) * (BATCH * HID);

        float acc[4][4];  // [comp][batch]
        const float* xgp = g_xg + (size_t)t * BATCH * G4;
#pragma unroll
        for (int ci = 0; ci < 4; ci++)
#pragma unroll
            for (int bi = 0; bi < 4; bi++)
                acc[ci][bi] = xgp[(size_t)(b0 + bi) * G4 + ci * HID + jglob] + bhv[ci];

        for (int k0 = 0; k0 < HID; k0 += 64) {
            // stage loads
            float4 hv[4];
            const float4* hp = (const float4*)(hb + (size_t)hl_b * HID + k0 + hl_q * 16);
#pragma unroll
            for (int i = 0; i < 4; i++) hv[i] = __ldcg(hp + i);

            float4 rv[8];
            const float4* rp = (const float4*)(Rbase + k0);
#pragma unroll
            for (int i = 0; i < 8; i++) rv[i] = __ldg(rp + i);

            __syncthreads();
#pragma unroll
            for (int i = 0; i < 4; i++) {
                int kk = hl_q * 16 + i * 4;
                h_s[kk + 0][hl_b] = hv[i].x;
                h_s[kk + 1][hl_b] = hv[i].y;
                h_s[kk + 2][hl_b] = hv[i].z;
                h_s[kk + 3][hl_b] = hv[i].w;
            }
#pragma unroll
            for (int i = 0; i < 8; i++) {
                int kk = rl_half * 32 + i * 4;
                r_s[kk + 0][rl_q] = rv[i].x;
                r_s[kk + 1][rl_q] = rv[i].y;
                r_s[kk + 2][rl_q] = rv[i].z;
                r_s[kk + 3][rl_q] = rv[i].w;
            }
            __syncthreads();

#pragma unroll 8
            for (int kk = 0; kk < 64; kk++) {
                float r4[4], h4[4];
                *(float4*)r4 = *(const float4*)&r_s[kk][jj * 4];
                *(float4*)h4 = *(const float4*)&h_s[kk][b0];
#pragma unroll
                for (int ci = 0; ci < 4; ci++)
#pragma unroll
                    for (int bi = 0; bi < 4; bi++)
                        acc[ci][bi] += r4[ci] * h4[bi];
            }
        }

        // gate nonlinearity + cell update (comp order: i, o, z, f)
#pragma unroll
        for (int bi = 0; bi < 4; bi++) {
            float ig = sigmoidf_(acc[0][bi]);
            float og = sigmoidf_(acc[1][bi]);
            float zg = sigmoidf_(acc[2][bi]);
            float fg = sigmoidf_(acc[3][bi]);
            c_reg[bi] = c_reg[bi] * fg + zg - ig;
            float hv = sigmoidf_(c_reg[bi]) - og;
            hlast[bi] = hv;
            __stcg(hn + (size_t)(b0 + bi) * HID + jglob, hv);
            out[((size_t)t * BATCH + (b0 + bi)) * HID + jglob] = hv;
        }

        phase++;
        grid_barrier(NCTA_REC, phase);
    }

    // final states
#pragma unroll
    for (int bi = 0; bi < 4; bi++) {
        hfin[(b0 + bi) * HID + jglob] = hlast[bi];
        cfin[(b0 + bi) * HID + jglob] = c_reg[bi];
    }
}

// ---------------------------------------------------------------------------
// Launch: proj0 -> recur0 -> proj1 -> recur1
// d_out layout: out[T,B,H], h_final[L,B,H], c_final[L,B,H]
// ---------------------------------------------------------------------------
extern "C" void kernel_launch(void* const* d_in, const int* in_sizes, int n_in,
                              void* d_out, int out_size)
{
    const float* x   = (const float*)d_in[0];
    const float* h0  = (const float*)d_in[1];
    const float* c0  = (const float*)d_in[2];
    const float* W0  = (const float*)d_in[3];
    const float* R0  = (const float*)d_in[4];
    const float* bi0 = (const float*)d_in[5];
    const float* bh0 = (const float*)d_in[6];
    const float* W1  = (const float*)d_in[7];
    const float* R1  = (const float*)d_in[8];
    const float* bi1 = (const float*)d_in[9];
    const float* bh1 = (const float*)d_in[10];

    float* outp    = (float*)d_out;
    float* out_seq = outp;
    float* hfin    = outp + (size_t)T_STEPS * BATCH * HID;
    float* cfin    = hfin + (size_t)NLAYERS * BATCH * HID;

    dim3 pg(G4 / 64, (T_STEPS * BATCH) / 64);

    // layer 0
    proj_kernel<<<pg, 128>>>(x, 0, W0, bi0);
    recur_kernel<<<NCTA_REC, REC_THREADS>>>(R0, bh0, h0, c0, 0, nullptr,
                                            hfin, cfin);
    // layer 1
    proj_kernel<<<pg, 128>>>(x, 1, W1, bi1);
    recur_kernel<<<NCTA_REC, REC_THREADS>>>(R1, bh1,
                                            h0 + BATCH * HID, c0 + BATCH * HID,
                                            1, out_seq,
                                            hfin + BATCH * HID, cfin + BATCH * HID);
}

// round 3
// speedup vs baseline: 1.3871x; 1.3871x over previous
#include <cuda_runtime.h>
#include <cstdint>

// Problem constants
#define T_STEPS 512
#define BATCH   32
#define HID     1024
#define G4      4096   // 4*HID
#define NLAYERS 2

#define NCTA_REC    128
#define REC_THREADS 128
#define CK          64          // k-chunk size streamed through smem
#define NCH         (HID/CK)    // 16 chunks
#define RPAD        68          // padded row stride (floats), 272B, 16B aligned

// ---------------------------------------------------------------------------
// Static device scratch
// ---------------------------------------------------------------------------
__device__ float g_xg[(size_t)T_STEPS * G4 * BATCH];    // 256 MB: [t][gate q][batch]  (TRANSPOSED)
__device__ float g_out0[(size_t)T_STEPS * BATCH * HID]; // 64 MB: layer-0 output sequence [t][b][j]
__device__ float g_hbuf[2 * BATCH * HID];               // double-buffered hidden state [b][j]
__device__ unsigned g_bar_count = 0;
__device__ unsigned g_bar_sense = 0;

__device__ __forceinline__ float sigmoidf_(float x) {
    return 1.0f / (1.0f + __expf(-x));
}

// cp.async helpers (Ampere+ LDGSTS, .cg = L2-only, 16B)
__device__ __forceinline__ void cp16(uint32_t dst_smem, const void* src) {
    asm volatile("cp.async.cg.shared.global [%0], [%1], 16;" :: "r"(dst_smem), "l"(src));
}
__device__ __forceinline__ void cp_commit() {
    asm volatile("cp.async.commit_group;");
}
template<int N> __device__ __forceinline__ void cp_wait() {
    asm volatile("cp.async.wait_group %0;" :: "n"(N));
}

// Grid barrier: sense with monotonic phase. Release via atomicExch; waiters
// poll with a plain volatile load (L2) -> no atomic-ALU serialization.
__device__ __forceinline__ void grid_barrier(unsigned nctas, unsigned phase) {
    __syncthreads();
    if (threadIdx.x == 0) {
        __threadfence();
        unsigned a = atomicAdd(&g_bar_count, 1u);
        if (a == nctas - 1u) {
            atomicExch(&g_bar_count, 0u);
            __threadfence();
            atomicExch(&g_bar_sense, phase);
        } else {
            while ((int)(*(volatile unsigned*)&g_bar_sense - phase) < 0) {
                __nanosleep(32);
            }
        }
    }
    __syncthreads();
}

// ---------------------------------------------------------------------------
// Projection GEMM: xg[t][n][b] = sum_k A[(t,b),k] * W[n,k] + bi[n]   (transposed epilogue)
// A: [16384, 1024], W: [4096, 1024]. 64x64 tile, 128 threads, 4x8 blocking.
// ---------------------------------------------------------------------------
__global__ __launch_bounds__(128) void proj_kernel(
    const float* __restrict__ x_in, int layer,
    const float* __restrict__ W, const float* __restrict__ bi)
{
    const float* A = (layer == 0) ? x_in : g_out0;

    __shared__ float a_s[32][64];
    __shared__ float b_s[32][64];

    const int tx = threadIdx.x;
    const int m0 = blockIdx.y * 64;
    const int n0 = blockIdx.x * 64;
    const int tm = tx >> 3;        // 0..15
    const int tn = tx & 7;         // 0..7
    const int lrow  = tx & 63;
    const int lhalf = tx >> 6;

    float acc[4][8];
#pragma unroll
    for (int i = 0; i < 4; i++)
#pragma unroll
        for (int j = 0; j < 8; j++) acc[i][j] = 0.0f;

    const float4* ap = (const float4*)(A + (size_t)(m0 + lrow) * HID + lhalf * 16);
    const float4* bp = (const float4*)(W + (size_t)(n0 + lrow) * HID + lhalf * 16);

    for (int k0 = 0; k0 < HID; k0 += 32) {
        float4 av[4], bv[4];
#pragma unroll
        for (int i = 0; i < 4; i++) { av[i] = __ldg(ap + i); bv[i] = __ldg(bp + i); }
        ap += 8; bp += 8;

        __syncthreads();
#pragma unroll
        for (int i = 0; i < 4; i++) {
            int kk = lhalf * 16 + i * 4;
            a_s[kk + 0][lrow] = av[i].x;
            a_s[kk + 1][lrow] = av[i].y;
            a_s[kk + 2][lrow] = av[i].z;
            a_s[kk + 3][lrow] = av[i].w;
            b_s[kk + 0][lrow] = bv[i].x;
            b_s[kk + 1][lrow] = bv[i].y;
            b_s[kk + 2][lrow] = bv[i].z;
            b_s[kk + 3][lrow] = bv[i].w;
        }
        __syncthreads();

#pragma unroll 8
        for (int kk = 0; kk < 32; kk++) {
            float a4[4], b8[8];
            *(float4*)a4      = *(const float4*)&a_s[kk][tm * 4];
            *(float4*)&b8[0]  = *(const float4*)&b_s[kk][tn * 8];
            *(float4*)&b8[4]  = *(const float4*)&b_s[kk][tn * 8 + 4];
#pragma unroll
            for (int mi = 0; mi < 4; mi++)
#pragma unroll
                for (int ni = 0; ni < 8; ni++)
                    acc[mi][ni] += a4[mi] * b8[ni];
        }
    }

    float bias8[8];
#pragma unroll
    for (int ni = 0; ni < 8; ni++) bias8[ni] = __ldg(bi + n0 + tn * 8 + ni);

    // Transposed epilogue: g_xg[t][n][b], with m = t*32 + b
#pragma unroll
    for (int mi = 0; mi < 4; mi++) {
        int m = m0 + tm * 4 + mi;
        int t = m >> 5;
        int b = m & 31;
        float* base = g_xg + (size_t)t * G4 * BATCH + b;
#pragma unroll
        for (int ni = 0; ni < 8; ni++) {
            int n = n0 + tn * 8 + ni;
            base[(size_t)n * BATCH] = acc[mi][ni] + bias8[ni];
        }
    }
}

// ---------------------------------------------------------------------------
// Persistent recurrence kernel v2.
// 128 CTAs x 128 threads. CTA owns j in [cta*8, cta*8+8), all 4 comps
// (32 R-rows). Thread tile: 4 comps x 1 j x 2 batches (8 accumulators).
// R and h streamed through double-buffered smem chunks via cp.async.cg.
// ---------------------------------------------------------------------------
__global__ __launch_bounds__(REC_THREADS) void recur_kernel(
    const float* __restrict__ Rm, const float* __restrict__ bh,
    const float* __restrict__ h0l, const float* __restrict__ c0l,
    int layer, float* __restrict__ out_g,
    float* __restrict__ hfin, float* __restrict__ cfin)
{
    __shared__ float R_s[2][32][RPAD];
    __shared__ float h_s[2][32][RPAD];

    float* out = (layer == 0) ? g_out0 : out_g;

    const int tx  = threadIdx.x;
    const int cta = blockIdx.x;
    const int jj    = tx >> 4;          // 0..7
    const int gq    = tx & 15;          // 0..15
    const int b0    = gq * 2;           // 2 batches per thread
    const int jglob = cta * 8 + jj;

    unsigned phase = *(volatile unsigned*)&g_bar_sense;  // stable at entry

    // init h buffer 0 from h0: 16384 threads x 2 floats
    {
        int gid = cta * REC_THREADS + tx;
        float2 v = *(const float2*)(h0l + (size_t)gid * 2);
        __stcg((float2*)(g_hbuf + (size_t)gid * 2), v);
    }

    float c_reg[2], bhv[4];
#pragma unroll
    for (int bi = 0; bi < 2; bi++) c_reg[bi] = c0l[(b0 + bi) * HID + jglob];
#pragma unroll
    for (int ci = 0; ci < 4; ci++) bhv[ci] = bh[ci * HID + jglob];

    // cp.async task decode: 512 16B-granules per tile (32 rows x 16), 4 per thread.
    const float* rsrc[4];
    uint32_t rdst[2][4], hdst[2][4];
    int hoff[4];
    uint32_t Rbase = (uint32_t)__cvta_generic_to_shared(&R_s[0][0][0]);
    uint32_t Hbase = (uint32_t)__cvta_generic_to_shared(&h_s[0][0][0]);
#pragma unroll
    for (int i = 0; i < 4; i++) {
        int task = tx + i * REC_THREADS;       // 0..511
        int r  = task >> 4;                    // row 0..31
        int gg = task & 15;                    // granule in row
        int grow = (r >> 3) * HID + cta * 8 + (r & 7);   // global R row (comp*H + j)
        rsrc[i] = Rm + (size_t)grow * HID + gg * 4;
        hoff[i] = r * HID + gg * 4;            // h: row r = batch index
#pragma unroll
        for (int buf = 0; buf < 2; buf++) {
            rdst[buf][i] = Rbase + (uint32_t)(((buf * 32 + r) * RPAD + gg * 4) * 4);
            hdst[buf][i] = Hbase + (uint32_t)(((buf * 32 + r) * RPAD + gg * 4) * 4);
        }
    }

    // xg prefetch for t=0 (layout [t][q][b])
    float2 pf[4];
#pragma unroll
    for (int ci = 0; ci < 4; ci++)
        pf[ci] = *(const float2*)(g_xg + ((size_t)ci * HID + jglob) * BATCH + b0);

    float hl[2] = {0.f, 0.f};

    phase++;
    grid_barrier(NCTA_REC, phase);

    for (int t = 0; t < T_STEPS; t++) {
        const float* hb = g_hbuf + (t & 1) * (BATCH * HID);
        float*       hn = g_hbuf + ((t + 1) & 1) * (BATCH * HID);

        float acc[4][2];
#pragma unroll
        for (int ci = 0; ci < 4; ci++) {
            acc[ci][0] = pf[ci].x + bhv[ci];
            acc[ci][1] = pf[ci].y + bhv[ci];
        }

        // issue chunk 0
#pragma unroll
        for (int i = 0; i < 4; i++) cp16(rdst[0][i], rsrc[i]);
#pragma unroll
        for (int i = 0; i < 4; i++) cp16(hdst[0][i], hb + hoff[i]);
        cp_commit();

        for (int cchunk = 0; cchunk < NCH; cchunk++) {
            const int buf = cchunk & 1;
            if (cchunk + 1 < NCH) {
                const int nbuf = (cchunk + 1) & 1;
                const int ko = (cchunk + 1) * CK;
#pragma unroll
                for (int i = 0; i < 4; i++) cp16(rdst[nbuf][i], rsrc[i] + ko);
#pragma unroll
                for (int i = 0; i < 4; i++) cp16(hdst[nbuf][i], hb + hoff[i] + ko);
                cp_commit();
                cp_wait<1>();
            } else {
                cp_wait<0>();
            }
            __syncthreads();

#pragma unroll
            for (int k4 = 0; k4 < CK / 4; k4++) {
                const int kk = k4 * 4;
                float4 hv0 = *(const float4*)&h_s[buf][b0][kk];
                float4 hv1 = *(const float4*)&h_s[buf][b0 + 1][kk];
#pragma unroll
                for (int ci = 0; ci < 4; ci++) {
                    float4 rv = *(const float4*)&R_s[buf][ci * 8 + jj][kk];
                    acc[ci][0] = fmaf(rv.x, hv0.x, acc[ci][0]);
                    acc[ci][0] = fmaf(rv.y, hv0.y, acc[ci][0]);
                    acc[ci][0] = fmaf(rv.z, hv0.z, acc[ci][0]);
                    acc[ci][0] = fmaf(rv.w, hv0.w, acc[ci][0]);
                    acc[ci][1] = fmaf(rv.x, hv1.x, acc[ci][1]);
                    acc[ci][1] = fmaf(rv.y, hv1.y, acc[ci][1]);
                    acc[ci][1] = fmaf(rv.z, hv1.z, acc[ci][1]);
                    acc[ci][1] = fmaf(rv.w, hv1.w, acc[ci][1]);
                }
            }
            __syncthreads();
        }

        // gates (comp order: i, o, z, f) + cell update + h write
#pragma unroll
        for (int bi = 0; bi < 2; bi++) {
            float ig = sigmoidf_(acc[0][bi]);
            float og = sigmoidf_(acc[1][bi]);
            float zg = sigmoidf_(acc[2][bi]);
            float fg = sigmoidf_(acc[3][bi]);
            c_reg[bi] = c_reg[bi] * fg + zg - ig;
            float hv = sigmoidf_(c_reg[bi]) - og;
            hl[bi] = hv;
            __stcg(hn + (size_t)(b0 + bi) * HID + jglob, hv);
            out[((size_t)t * BATCH + (b0 + bi)) * HID + jglob] = hv;
        }

        // prefetch next step's xg before the barrier (overlaps spin with DRAM)
        {
            int tn = (t + 1 < T_STEPS) ? (t + 1) : t;
            const float* xb = g_xg + (size_t)tn * G4 * BATCH;
#pragma unroll
            for (int ci = 0; ci < 4; ci++)
                pf[ci] = *(const float2*)(xb + ((size_t)ci * HID + jglob) * BATCH + b0);
        }

        phase++;
        grid_barrier(NCTA_REC, phase);
    }

    // final states
#pragma unroll
    for (int bi = 0; bi < 2; bi++) {
        hfin[(b0 + bi) * HID + jglob] = hl[bi];
        cfin[(b0 + bi) * HID + jglob] = c_reg[bi];
    }
}

// ---------------------------------------------------------------------------
// Launch: proj0 -> recur0 -> proj1 -> recur1
// d_out layout: out[T,B,H], h_final[L,B,H], c_final[L,B,H]
// ---------------------------------------------------------------------------
extern "C" void kernel_launch(void* const* d_in, const int* in_sizes, int n_in,
                              void* d_out, int out_size)
{
    const float* x   = (const float*)d_in[0];
    const float* h0  = (const float*)d_in[1];
    const float* c0  = (const float*)d_in[2];
    const float* W0  = (const float*)d_in[3];
    const float* R0  = (const float*)d_in[4];
    const float* bi0 = (const float*)d_in[5];
    const float* bh0 = (const float*)d_in[6];
    const float* W1  = (const float*)d_in[7];
    const float* R1  = (const float*)d_in[8];
    const float* bi1 = (const float*)d_in[9];
    const float* bh1 = (const float*)d_in[10];

    float* outp    = (float*)d_out;
    float* out_seq = outp;
    float* hfin    = outp + (size_t)T_STEPS * BATCH * HID;
    float* cfin    = hfin + (size_t)NLAYERS * BATCH * HID;

    dim3 pg(G4 / 64, (T_STEPS * BATCH) / 64);

    // layer 0
    proj_kernel<<<pg, 128>>>(x, 0, W0, bi0);
    recur_kernel<<<NCTA_REC, REC_THREADS>>>(R0, bh0, h0, c0, 0, nullptr,
                                            hfin, cfin);
    // layer 1
    proj_kernel<<<pg, 128>>>(x, 1, W1, bi1);
    recur_kernel<<<NCTA_REC, REC_THREADS>>>(R1, bh1,
                                            h0 + BATCH * HID, c0 + BATCH * HID,
                                            1, out_seq,
                                            hfin + BATCH * HID, cfin + BATCH * HID);
}

// round 4
// speedup vs baseline: 1.9329x; 1.3934x over previous
#include <cuda_runtime.h>
#include <cstdint>

// Problem constants
#define T_STEPS 512
#define BATCH   32
#define HID     1024
#define G4      4096   // 4*HID
#define NLAYERS 2

#define NCTA_REC    128
#define REC_THREADS 256
#define CK          32          // k-chunk per group
#define NCH         16          // chunks per 512-k half
#define PAD         36          // padded row stride (floats), 144B, 16B aligned

// ---------------------------------------------------------------------------
// Static device scratch
// ---------------------------------------------------------------------------
__device__ float g_xg[(size_t)T_STEPS * G4 * BATCH];    // [t][gate q][batch]  (transposed)
__device__ float g_out0[(size_t)T_STEPS * BATCH * HID]; // layer-0 output [t][b][j]
__device__ float g_hbuf[2 * BATCH * HID];               // double-buffered hidden state [b][j]
__device__ unsigned g_bar_count = 0;
__device__ unsigned g_bar_sense = 0;

__device__ __forceinline__ float sigmoidf_(float x) {
    return 1.0f / (1.0f + __expf(-x));
}

__device__ __forceinline__ void cp16(uint32_t dst_smem, const void* src) {
    asm volatile("cp.async.cg.shared.global [%0], [%1], 16;" :: "r"(dst_smem), "l"(src));
}
__device__ __forceinline__ void cp_commit() {
    asm volatile("cp.async.commit_group;");
}
template<int N> __device__ __forceinline__ void cp_wait() {
    asm volatile("cp.async.wait_group %0;" :: "n"(N));
}
__device__ __forceinline__ void named_bar(int id) {
    asm volatile("bar.sync %0, 128;" :: "r"(id) : "memory");
}

// Grid barrier: atomic arrive, L2 volatile-poll release. Monotonic phase.
__device__ __forceinline__ void grid_barrier(unsigned nctas, unsigned phase) {
    __syncthreads();
    if (threadIdx.x == 0) {
        __threadfence();
        unsigned a = atomicAdd(&g_bar_count, 1u);
        if (a == nctas - 1u) {
            atomicExch(&g_bar_count, 0u);
            __threadfence();
            atomicExch(&g_bar_sense, phase);
        } else {
            while ((int)(*(volatile unsigned*)&g_bar_sense - phase) < 0) {
                __nanosleep(32);
            }
        }
    }
    __syncthreads();
}

// ---------------------------------------------------------------------------
// Projection GEMM: xg[t][n][b] = sum_k A[(t,b),k] * W[n,k] + bi[n]
// ---------------------------------------------------------------------------
__global__ __launch_bounds__(128) void proj_kernel(
    const float* __restrict__ x_in, int layer,
    const float* __restrict__ W, const float* __restrict__ bi)
{
    const float* A = (layer == 0) ? x_in : g_out0;

    __shared__ float a_s[32][64];
    __shared__ float b_s[32][64];

    const int tx = threadIdx.x;
    const int m0 = blockIdx.y * 64;
    const int n0 = blockIdx.x * 64;
    const int tm = tx >> 3;
    const int tn = tx & 7;
    const int lrow  = tx & 63;
    const int lhalf = tx >> 6;

    float acc[4][8];
#pragma unroll
    for (int i = 0; i < 4; i++)
#pragma unroll
        for (int j = 0; j < 8; j++) acc[i][j] = 0.0f;

    const float4* ap = (const float4*)(A + (size_t)(m0 + lrow) * HID + lhalf * 16);
    const float4* bp = (const float4*)(W + (size_t)(n0 + lrow) * HID + lhalf * 16);

    for (int k0 = 0; k0 < HID; k0 += 32) {
        float4 av[4], bv[4];
#pragma unroll
        for (int i = 0; i < 4; i++) { av[i] = __ldg(ap + i); bv[i] = __ldg(bp + i); }
        ap += 8; bp += 8;

        __syncthreads();
#pragma unroll
        for (int i = 0; i < 4; i++) {
            int kk = lhalf * 16 + i * 4;
            a_s[kk + 0][lrow] = av[i].x;
            a_s[kk + 1][lrow] = av[i].y;
            a_s[kk + 2][lrow] = av[i].z;
            a_s[kk + 3][lrow] = av[i].w;
            b_s[kk + 0][lrow] = bv[i].x;
            b_s[kk + 1][lrow] = bv[i].y;
            b_s[kk + 2][lrow] = bv[i].z;
            b_s[kk + 3][lrow] = bv[i].w;
        }
        __syncthreads();

#pragma unroll 8
        for (int kk = 0; kk < 32; kk++) {
            float a4[4], b8[8];
            *(float4*)a4      = *(const float4*)&a_s[kk][tm * 4];
            *(float4*)&b8[0]  = *(const float4*)&b_s[kk][tn * 8];
            *(float4*)&b8[4]  = *(const float4*)&b_s[kk][tn * 8 + 4];
#pragma unroll
            for (int mi = 0; mi < 4; mi++)
#pragma unroll
                for (int ni = 0; ni < 8; ni++)
                    acc[mi][ni] += a4[mi] * b8[ni];
        }
    }

    float bias8[8];
#pragma unroll
    for (int ni = 0; ni < 8; ni++) bias8[ni] = __ldg(bi + n0 + tn * 8 + ni);

    // Transposed epilogue: g_xg[t][n][b], with m = t*32 + b
#pragma unroll
    for (int mi = 0; mi < 4; mi++) {
        int m = m0 + tm * 4 + mi;
        int t = m >> 5;
        int b = m & 31;
        float* base = g_xg + (size_t)t * G4 * BATCH + b;
#pragma unroll
        for (int ni = 0; ni < 8; ni++) {
            int n = n0 + tn * 8 + ni;
            base[(size_t)n * BATCH] = acc[mi][ni] + bias8[ni];
        }
    }
}

// ---------------------------------------------------------------------------
// Persistent recurrence v3: split-K.
// 128 CTAs x 256 threads. Group g (128 thr) covers k in [g*512, g*512+512).
// CTA owns j-block of 8 (32 R-rows: 4 comps); thread: 4 comps x 1 j x 2
// batches (q, q+16). Partials merged via smem once per step.
// ---------------------------------------------------------------------------
__global__ __launch_bounds__(REC_THREADS) void recur_kernel(
    const float* __restrict__ Rm, const float* __restrict__ bh,
    const float* __restrict__ h0l, const float* __restrict__ c0l,
    int layer, float* __restrict__ out_g,
    float* __restrict__ hfin, float* __restrict__ cfin)
{
    __shared__ float  R_s[2][2][32][PAD];   // [grp][buf][row][k]
    __shared__ float  h_s[2][2][32][PAD];   // [grp][buf][batch][k]
    __shared__ float2 red_s[4][8][16];      // [comp][jj][gq] partials from grp 1

    float* out = (layer == 0) ? g_out0 : out_g;

    const int tx   = threadIdx.x;
    const int cta  = blockIdx.x;
    const int grp  = tx >> 7;         // 0 or 1 (k-half)
    const int gtx  = tx & 127;
    const int jj   = gtx >> 4;        // 0..7
    const int gq   = gtx & 15;        // 0..15
    const int bA   = gq;
    const int bB   = gq + 16;
    const int jglob = cta * 8 + jj;
    const int barid = 1 + grp;

    unsigned phase = *(volatile unsigned*)&g_bar_sense;

    // init h buffer 0 from h0: 32768 threads x 1 float
    {
        int gid = cta * REC_THREADS + tx;
        __stcg(g_hbuf + gid, h0l[gid]);
    }

    float c_reg[2] = {0.f, 0.f}, bhv[4] = {0.f, 0.f, 0.f, 0.f};
    float xA[4], xB[4];
    if (grp == 0) {
        c_reg[0] = c0l[bA * HID + jglob];
        c_reg[1] = c0l[bB * HID + jglob];
#pragma unroll
        for (int ci = 0; ci < 4; ci++) bhv[ci] = bh[ci * HID + jglob];
        // xg prefetch for t=0
#pragma unroll
        for (int ci = 0; ci < 4; ci++) {
            const float* p = g_xg + ((size_t)ci * HID + jglob) * BATCH;
            xA[ci] = p[bA];
            xB[ci] = p[bB];
        }
    }

    // loader task decode: per chunk, 32 rows x 8 granules = 256 tasks, 2/thread
    const float* rsrc[2];
    int hoff[2];
    uint32_t rdst[2][2], hdst[2][2];
    uint32_t Rbase = (uint32_t)__cvta_generic_to_shared(&R_s[0][0][0][0]);
    uint32_t Hbase = (uint32_t)__cvta_generic_to_shared(&h_s[0][0][0][0]);
#pragma unroll
    for (int i = 0; i < 2; i++) {
        int task = gtx + i * 128;
        int r  = task >> 3;                    // 0..31
        int gg = task & 7;                     // granule in row
        int grow = (r >> 3) * HID + cta * 8 + (r & 7);
        rsrc[i] = Rm + (size_t)grow * HID + grp * 512 + gg * 4;
        hoff[i] = r * HID + grp * 512 + gg * 4;
#pragma unroll
        for (int buf = 0; buf < 2; buf++) {
            uint32_t off = (uint32_t)((((grp * 2 + buf) * 32 + r) * PAD + gg * 4) * 4);
            rdst[buf][i] = Rbase + off;
            hdst[buf][i] = Hbase + off;
        }
    }

    float hl[2] = {0.f, 0.f};

    phase++;
    grid_barrier(NCTA_REC, phase);

    for (int t = 0; t < T_STEPS; t++) {
        const float* hb = g_hbuf + (t & 1) * (BATCH * HID);
        float*       hn = g_hbuf + ((t + 1) & 1) * (BATCH * HID);

        float acc[4][2];
#pragma unroll
        for (int ci = 0; ci < 4; ci++) {
            acc[ci][0] = (grp == 0) ? (xA[ci] + bhv[ci]) : 0.f;
            acc[ci][1] = (grp == 0) ? (xB[ci] + bhv[ci]) : 0.f;
        }

        // prologue: issue chunks 0 and 1
#pragma unroll
        for (int i = 0; i < 2; i++) { cp16(rdst[0][i], rsrc[i]); cp16(hdst[0][i], hb + hoff[i]); }
        cp_commit();
#pragma unroll
        for (int i = 0; i < 2; i++) { cp16(rdst[1][i], rsrc[i] + CK); cp16(hdst[1][i], hb + hoff[i] + CK); }
        cp_commit();

        for (int c = 0; c < NCH; c++) {
            const int buf = c & 1;
            if (c < NCH - 1) cp_wait<1>(); else cp_wait<0>();
            named_bar(barid);

#pragma unroll
            for (int k4 = 0; k4 < CK / 4; k4++) {
                const int kk = k4 * 4;
                float4 hv0 = *(const float4*)&h_s[grp][buf][bA][kk];
                float4 hv1 = *(const float4*)&h_s[grp][buf][bB][kk];
#pragma unroll
                for (int ci = 0; ci < 4; ci++) {
                    float4 rv = *(const float4*)&R_s[grp][buf][ci * 8 + jj][kk];
                    acc[ci][0] = fmaf(rv.x, hv0.x, acc[ci][0]);
                    acc[ci][0] = fmaf(rv.y, hv0.y, acc[ci][0]);
                    acc[ci][0] = fmaf(rv.z, hv0.z, acc[ci][0]);
                    acc[ci][0] = fmaf(rv.w, hv0.w, acc[ci][0]);
                    acc[ci][1] = fmaf(rv.x, hv1.x, acc[ci][1]);
                    acc[ci][1] = fmaf(rv.y, hv1.y, acc[ci][1]);
                    acc[ci][1] = fmaf(rv.z, hv1.z, acc[ci][1]);
                    acc[ci][1] = fmaf(rv.w, hv1.w, acc[ci][1]);
                }
            }
            named_bar(barid);

            if (c + 2 < NCH) {
                const int ko = (c + 2) * CK;
#pragma unroll
                for (int i = 0; i < 2; i++) { cp16(rdst[buf][i], rsrc[i] + ko); cp16(hdst[buf][i], hb + hoff[i] + ko); }
                cp_commit();
            }
        }

        // merge k-halves
        if (grp == 1) {
#pragma unroll
            for (int ci = 0; ci < 4; ci++)
                red_s[ci][jj][gq] = make_float2(acc[ci][0], acc[ci][1]);
        }
        __syncthreads();

        if (grp == 0) {
#pragma unroll
            for (int ci = 0; ci < 4; ci++) {
                float2 p = red_s[ci][jj][gq];
                acc[ci][0] += p.x;
                acc[ci][1] += p.y;
            }
            // gates (comp order: i, o, z, f) + cell update + writes
            const int bidx[2] = {bA, bB};
#pragma unroll
            for (int bi = 0; bi < 2; bi++) {
                float ig = sigmoidf_(acc[0][bi]);
                float og = sigmoidf_(acc[1][bi]);
                float zg = sigmoidf_(acc[2][bi]);
                float fg = sigmoidf_(acc[3][bi]);
                c_reg[bi] = c_reg[bi] * fg + zg - ig;
                float hv = sigmoidf_(c_reg[bi]) - og;
                hl[bi] = hv;
                __stcg(hn + (size_t)bidx[bi] * HID + jglob, hv);
                out[((size_t)t * BATCH + bidx[bi]) * HID + jglob] = hv;
            }
            // prefetch next step's xg (overlaps barrier spin)
            int tnx = (t + 1 < T_STEPS) ? (t + 1) : t;
            const float* xb = g_xg + (size_t)tnx * G4 * BATCH;
#pragma unroll
            for (int ci = 0; ci < 4; ci++) {
                const float* p = xb + ((size_t)ci * HID + jglob) * BATCH;
                xA[ci] = p[bA];
                xB[ci] = p[bB];
            }
        }

        phase++;
        grid_barrier(NCTA_REC, phase);
    }

    if (grp == 0) {
        hfin[bA * HID + jglob] = hl[0];
        hfin[bB * HID + jglob] = hl[1];
        cfin[bA * HID + jglob] = c_reg[0];
        cfin[bB * HID + jglob] = c_reg[1];
    }
}

// ---------------------------------------------------------------------------
// Launch: proj0 -> recur0 -> proj1 -> recur1
// d_out layout: out[T,B,H], h_final[L,B,H], c_final[L,B,H]
// ---------------------------------------------------------------------------
extern "C" void kernel_launch(void* const* d_in, const int* in_sizes, int n_in,
                              void* d_out, int out_size)
{
    const float* x   = (const float*)d_in[0];
    const float* h0  = (const float*)d_in[1];
    const float* c0  = (const float*)d_in[2];
    const float* W0  = (const float*)d_in[3];
    const float* R0  = (const float*)d_in[4];
    const float* bi0 = (const float*)d_in[5];
    const float* bh0 = (const float*)d_in[6];
    const float* W1  = (const float*)d_in[7];
    const float* R1  = (const float*)d_in[8];
    const float* bi1 = (const float*)d_in[9];
    const float* bh1 = (const float*)d_in[10];

    float* outp    = (float*)d_out;
    float* out_seq = outp;
    float* hfin    = outp + (size_t)T_STEPS * BATCH * HID;
    float* cfin    = hfin + (size_t)NLAYERS * BATCH * HID;

    dim3 pg(G4 / 64, (T_STEPS * BATCH) / 64);

    // layer 0
    proj_kernel<<<pg, 128>>>(x, 0, W0, bi0);
    recur_kernel<<<NCTA_REC, REC_THREADS>>>(R0, bh0, h0, c0, 0, nullptr,
                                            hfin, cfin);
    // layer 1
    proj_kernel<<<pg, 128>>>(x, 1, W1, bi1);
    recur_kernel<<<NCTA_REC, REC_THREADS>>>(R1, bh1,
                                            h0 + BATCH * HID, c0 + BATCH * HID,
                                            1, out_seq,
                                            hfin + BATCH * HID, cfin + BATCH * HID);
}